// round 2
// baseline (speedup 1.0000x reference)
#include <cuda_runtime.h>
#include <cuda_fp16.h>
#include <math.h>

#define B     64
#define P     196
#define D     2048
#define A_DIM 512
#define H     512
#define E     512
#define V     10000
#define T     19
#define LCAP  20
#define XH    3072   /* E + D + H */
#define G4    2048   /* 4*H       */

// ---------------- scratch (device globals; no runtime allocation) -----------
__device__ __half g_featsh[(size_t)B*P*D];      // features in fp16 (51.4 MB)
__device__ __half g_att1h[(size_t)B*P*A_DIM];   // att1 in fp16    (12.8 MB)
__device__ float  g_meanf[B*D];
__device__ float  g_h[B*H];
__device__ float  g_c[B*H];
__device__ float  g_xh[B*XH];                   // [emb | awe | h]
__device__ float  g_att2[B*A_DIM];
__device__ float  g_gate[B*D];
__device__ float  g_e[B*P];
__device__ float  g_gparts[2*B*G4];             // K-split partials for gates
__device__ float  g_Wcat[(size_t)G4*XH];        // [W_ih | W_hh]   (25.2 MB)
__device__ float  g_bcat[G4];                   // b_ih + b_hh
__device__ float  g_emb[(size_t)B*T*E];         // gathered embeddings

// ---------------- one-time kernels ------------------------------------------
__global__ void k_f2h(const float* __restrict__ f)
{
    size_t i = (size_t)blockIdx.x * blockDim.x + threadIdx.x;
    size_t n4 = (size_t)B*P*D/4;
    if (i < n4) {
        float4 v = ((const float4*)f)[i];
        __half2* o = (__half2*)g_featsh + 2*i;
        o[0] = __floats2half2_rn(v.x, v.y);
        o[1] = __floats2half2_rn(v.z, v.w);
    }
}

__global__ void k_mean(const float* __restrict__ f)
{
    int i = blockIdx.x * blockDim.x + threadIdx.x;
    if (i < B*D) {
        int b = i >> 11, d = i & (D-1);
        const float* p = f + (size_t)b*P*D + d;
        float s = 0.f;
        #pragma unroll 4
        for (int q = 0; q < P; q++) s += p[(size_t)q*D];
        g_meanf[i] = s * (1.f/196.f);
    }
}

__global__ void k_emb(const float* __restrict__ emb, const int* __restrict__ captions)
{
    int i = blockIdx.x * blockDim.x + threadIdx.x;
    if (i < B*T*E) {
        int e  = i & (E-1);
        int bt = i >> 9;
        int b = bt / T, t = bt % T;
        int tok = captions[b*LCAP + t];
        g_emb[i] = emb[(size_t)tok*E + e];
    }
}

__global__ void k_wcat(const float* __restrict__ W_ih, const float* __restrict__ b_ih,
                       const float* __restrict__ W_hh, const float* __restrict__ b_hh)
{
    size_t i = (size_t)blockIdx.x * blockDim.x + threadIdx.x;
    if (i < (size_t)G4*XH) {
        int j = (int)(i / XH), k = (int)(i % XH);
        g_Wcat[i] = (k < E + D) ? W_ih[(size_t)j*(E+D) + k]
                                : W_hh[(size_t)j*H + (k - (E+D))];
        if (k == 0) g_bcat[j] = b_ih[j] + b_hh[j];
    }
}

__global__ void k_initxh()
{
    int i = blockIdx.x * blockDim.x + threadIdx.x;
    if (i < B*H) {
        int b = i >> 9, j = i & (H-1);
        g_xh[b*XH + j]         = g_emb[(size_t)(b*T + 0)*E + j];   // emb at t=0
        g_xh[b*XH + E + D + j] = g_h[i];                           // h0
    }
}

// ---------------- att1 GEMM: (B*P, A) = feats(B*P, D) @ enc_w(A, D)^T -------
// 64x64 tile, BK=16, 256 threads, 4x4 micro-tile, fp32 acc, fp16 store.
__global__ void k_att1(const float* __restrict__ feats,
                       const float* __restrict__ encw,
                       const float* __restrict__ encb)
{
    __shared__ float As[16][68];
    __shared__ float Ws[16][68];
    const int tid = threadIdx.x;
    const int m0 = blockIdx.x * 64;
    const int n0 = blockIdx.y * 64;
    const int lr = tid >> 2, lk = (tid & 3) * 4;
    const int tm4 = (tid >> 4) * 4, tn4 = (tid & 15) * 4;
    float acc[4][4] = {};
    for (int kc = 0; kc < D; kc += 16) {
        float4 a = *(const float4*)(feats + (size_t)(m0+lr)*D + kc + lk);
        float4 w = *(const float4*)(encw  + (size_t)(n0+lr)*D + kc + lk);
        __syncthreads();
        As[lk+0][lr]=a.x; As[lk+1][lr]=a.y; As[lk+2][lr]=a.z; As[lk+3][lr]=a.w;
        Ws[lk+0][lr]=w.x; Ws[lk+1][lr]=w.y; Ws[lk+2][lr]=w.z; Ws[lk+3][lr]=w.w;
        __syncthreads();
        #pragma unroll
        for (int kk = 0; kk < 16; kk++) {
            float4 av = *(const float4*)&As[kk][tm4];
            float4 wv = *(const float4*)&Ws[kk][tn4];
            acc[0][0]+=av.x*wv.x; acc[0][1]+=av.x*wv.y; acc[0][2]+=av.x*wv.z; acc[0][3]+=av.x*wv.w;
            acc[1][0]+=av.y*wv.x; acc[1][1]+=av.y*wv.y; acc[1][2]+=av.y*wv.z; acc[1][3]+=av.y*wv.w;
            acc[2][0]+=av.z*wv.x; acc[2][1]+=av.z*wv.y; acc[2][2]+=av.z*wv.z; acc[2][3]+=av.z*wv.w;
            acc[3][0]+=av.w*wv.x; acc[3][1]+=av.w*wv.y; acc[3][2]+=av.w*wv.z; acc[3][3]+=av.w*wv.w;
        }
    }
    #pragma unroll
    for (int r = 0; r < 4; r++)
        #pragma unroll
        for (int c = 0; c < 4; c++) {
            int m = m0 + tm4 + r, n = n0 + tn4 + c;
            g_att1h[(size_t)m*A_DIM + n] = __float2half(acc[r][c] + encb[n]);
        }
}

// ---------------- generic skinny GEMM: C(64,N) = A(64,K) @ W(N,K)^T ---------
// mode 0: C = acc + bias       mode 1: C = sigmoid(acc + bias)
// mode 2: masked write of y into out (bias added, zeroed when inactive)
// blockIdx.y = K-slice index (A/W offset by y*K, C offset by y*64*N)
__global__ void k_gemm64(const float* __restrict__ Ain, int ldA,
                         const float* __restrict__ W, int ldW,
                         const float* __restrict__ bias,
                         float* __restrict__ C,
                         int N, int K, int mode, int t,
                         const int* __restrict__ lengths,
                         float* __restrict__ outy)
{
    __shared__ float As[32][68];
    __shared__ float Ws[32][36];
    const int tid  = threadIdx.x;
    const int n0   = blockIdx.x * 32;
    const int koff = blockIdx.y * K;

    const int am = tid >> 2, akq = (tid & 3) * 4;
    const int wn = tid >> 3, wkq = (tid & 7) * 4;
    const bool wvalid = (n0 + wn) < N;

    const int tm4 = (tid >> 4) * 4;
    const int tn2 = (tid & 15) * 2;

    float acc00=0,acc01=0,acc10=0,acc11=0,acc20=0,acc21=0,acc30=0,acc31=0;

    for (int kc = 0; kc < K; kc += 32) {
        const float* ap = Ain + (size_t)am*ldA + koff + kc;
        float4 a0 = *(const float4*)(ap + akq);
        float4 a1 = *(const float4*)(ap + 16 + akq);
        float4 w0 = make_float4(0.f, 0.f, 0.f, 0.f);
        if (wvalid)
            w0 = *(const float4*)(W + (size_t)(n0+wn)*ldW + koff + kc + wkq);
        __syncthreads();
        As[akq+0][am]=a0.x; As[akq+1][am]=a0.y; As[akq+2][am]=a0.z; As[akq+3][am]=a0.w;
        As[16+akq+0][am]=a1.x; As[16+akq+1][am]=a1.y; As[16+akq+2][am]=a1.z; As[16+akq+3][am]=a1.w;
        Ws[wkq+0][wn]=w0.x; Ws[wkq+1][wn]=w0.y; Ws[wkq+2][wn]=w0.z; Ws[wkq+3][wn]=w0.w;
        __syncthreads();
        #pragma unroll
        for (int kk = 0; kk < 32; kk++) {
            float4 a = *(const float4*)&As[kk][tm4];
            float b0 = Ws[kk][tn2], b1 = Ws[kk][tn2+1];
            acc00 += a.x*b0; acc01 += a.x*b1;
            acc10 += a.y*b0; acc11 += a.y*b1;
            acc20 += a.z*b0; acc21 += a.z*b1;
            acc30 += a.w*b0; acc31 += a.w*b1;
        }
    }
    float vals[4][2] = {{acc00,acc01},{acc10,acc11},{acc20,acc21},{acc30,acc31}};
    #pragma unroll
    for (int r = 0; r < 4; r++)
        #pragma unroll
        for (int cc = 0; cc < 2; cc++) {
            int m = tm4 + r, n = n0 + tn2 + cc;
            if (n >= N) continue;
            float v = vals[r][cc];
            if (bias) v += bias[n];
            if (mode == 1) v = 1.f / (1.f + expf(-v));
            if (mode == 2) {
                int act = t < (lengths[m] - 1);
                outy[(size_t)m*T*V + (size_t)t*V + n] = act ? v : 0.f;
            } else {
                C[(size_t)blockIdx.y*64*N + (size_t)m*N + n] = v;
            }
        }
}

// ---------------- e[b,p] = att_w . relu(att1[b,p,:] + att2[b,:]) + att_b ----
__global__ void k_e(const float* __restrict__ attw, const float* __restrict__ attb)
{
    int gw = (blockIdx.x * blockDim.x + threadIdx.x) >> 5;
    int lane = threadIdx.x & 31;
    if (gw >= B*P) return;
    int b = gw / P;
    const __half* a1 = g_att1h + (size_t)gw * A_DIM;
    const float*  a2 = g_att2  + b * A_DIM;
    float s = 0.f;
    #pragma unroll 4
    for (int a = lane; a < A_DIM; a += 32) {
        float v = __half2float(a1[a]) + a2[a];
        if (v > 0.f) s += v * attw[a];
    }
    #pragma unroll
    for (int o = 16; o; o >>= 1) s += __shfl_xor_sync(0xffffffffu, s, o);
    if (lane == 0) g_e[gw] = s + attb[0];
}

// ---------------- softmax(e) -> alpha; awe = gate * (alpha @ feats) ----------
// grid (B, 4): block (b, d-chunk of 512); also writes masked alpha output.
__global__ void k_awe(const int* __restrict__ lengths, float* __restrict__ out_alpha, int t)
{
    int b = blockIdx.x, chunk = blockIdx.y, tid = threadIdx.x;
    __shared__ float sred[256];
    __shared__ float sal[P];
    float ev = (tid < P) ? g_e[b*P + tid] : -1e30f;
    sred[tid] = ev; __syncthreads();
    for (int s = 128; s > 0; s >>= 1) { if (tid < s) sred[tid] = fmaxf(sred[tid], sred[tid+s]); __syncthreads(); }
    float mx = sred[0]; __syncthreads();
    float ex = (tid < P) ? expf(ev - mx) : 0.f;
    sred[tid] = ex; __syncthreads();
    for (int s = 128; s > 0; s >>= 1) { if (tid < s) sred[tid] += sred[tid+s]; __syncthreads(); }
    float inv = 1.f / sred[0];
    if (tid < P) sal[tid] = ex * inv;
    __syncthreads();

    const __half2* fp2 = (const __half2*)g_featsh + (size_t)b*P*(D/2) + chunk*256 + tid;
    float2 acc = make_float2(0.f, 0.f);
    #pragma unroll 4
    for (int p = 0; p < P; p++) {
        float2 f = __half22float2(fp2[(size_t)p*(D/2)]);
        float al = sal[p];
        acc.x += al * f.x; acc.y += al * f.y;
    }
    int d = chunk*512 + 2*tid;
    acc.x *= g_gate[b*D + d];
    acc.y *= g_gate[b*D + d + 1];
    g_xh[b*XH + E + d]     = acc.x;
    g_xh[b*XH + E + d + 1] = acc.y;

    if (chunk == 0 && tid < P) {
        int act = t < (lengths[b] - 1);
        out_alpha[((size_t)b*T + t)*P + tid] = act ? sal[tid] : 0.f;
    }
}

// ---------------- LSTM pointwise update + next-step emb staging -------------
__global__ void k_lstm(int t)
{
    int i = blockIdx.x * blockDim.x + threadIdx.x;
    if (i >= B*H) return;
    int b = i >> 9, j = i & (H-1);
    const float* p0 = g_gparts + (size_t)b*G4;
    const float* p1 = g_gparts + (size_t)B*G4 + (size_t)b*G4;
    float gi = p0[j]       + p1[j]       + g_bcat[j];
    float gf = p0[j +   H] + p1[j +   H] + g_bcat[j +   H];
    float gg = p0[j + 2*H] + p1[j + 2*H] + g_bcat[j + 2*H];
    float go = p0[j + 3*H] + p1[j + 3*H] + g_bcat[j + 3*H];
    float si = 1.f / (1.f + expf(-gi));
    float sf = 1.f / (1.f + expf(-gf));
    float so = 1.f / (1.f + expf(-go));
    float c2 = sf * g_c[i] + si * tanhf(gg);
    float h2 = so * tanhf(c2);
    g_c[i] = c2;
    g_h[i] = h2;
    g_xh[b*XH + E + D + j] = h2;
    if (t + 1 < T) g_xh[b*XH + j] = g_emb[(size_t)(b*T + (t+1))*E + j];
}

// ---------------- host driver ------------------------------------------------
extern "C" void kernel_launch(void* const* d_in, const int* in_sizes, int n_in,
                              void* d_out, int out_size)
{
    const float* features = (const float*)d_in[0];
    const int*   captions = (const int*)  d_in[1];
    const int*   lengths  = (const int*)  d_in[2];
    const float* emb      = (const float*)d_in[3];
    const float* W_ih     = (const float*)d_in[4];
    const float* b_ih     = (const float*)d_in[5];
    const float* W_hh     = (const float*)d_in[6];
    const float* b_hh     = (const float*)d_in[7];
    const float* h_fc_w   = (const float*)d_in[8];
    const float* h_fc_b   = (const float*)d_in[9];
    const float* c_fc_w   = (const float*)d_in[10];
    const float* c_fc_b   = (const float*)d_in[11];
    const float* f_beta_w = (const float*)d_in[12];
    const float* f_beta_b = (const float*)d_in[13];
    const float* cls_w    = (const float*)d_in[14];
    const float* cls_b    = (const float*)d_in[15];
    const float* enc_w    = (const float*)d_in[16];
    const float* enc_b    = (const float*)d_in[17];
    const float* dec_w    = (const float*)d_in[18];
    const float* dec_b    = (const float*)d_in[19];
    const float* att_w    = (const float*)d_in[20];
    const float* att_b    = (const float*)d_in[21];

    float* outy = (float*)d_out;
    float* outa = outy + (size_t)B*T*V;

    float *p_meanf, *p_h, *p_c, *p_xh, *p_att2, *p_gate, *p_gparts, *p_Wcat;
    cudaGetSymbolAddress((void**)&p_meanf,  g_meanf);
    cudaGetSymbolAddress((void**)&p_h,      g_h);
    cudaGetSymbolAddress((void**)&p_c,      g_c);
    cudaGetSymbolAddress((void**)&p_xh,     g_xh);
    cudaGetSymbolAddress((void**)&p_att2,   g_att2);
    cudaGetSymbolAddress((void**)&p_gate,   g_gate);
    cudaGetSymbolAddress((void**)&p_gparts, g_gparts);
    cudaGetSymbolAddress((void**)&p_Wcat,   g_Wcat);

    // ---- one-time preprocessing ----
    k_f2h <<<(int)(((size_t)B*P*D/4 + 255)/256), 256>>>(features);
    k_mean<<<(B*D + 255)/256, 256>>>(features);
    k_emb <<<(B*T*E + 255)/256, 256>>>(emb, captions);
    k_wcat<<<(int)(((size_t)G4*XH + 255)/256), 256>>>(W_ih, b_ih, W_hh, b_hh);
    // h0 / c0
    k_gemm64<<<dim3(H/32, 1), 256>>>(p_meanf, D, h_fc_w, D, h_fc_b, p_h, H, D, 0, 0, lengths, outy);
    k_gemm64<<<dim3(H/32, 1), 256>>>(p_meanf, D, c_fc_w, D, c_fc_b, p_c, H, D, 0, 0, lengths, outy);
    k_initxh<<<(B*H + 255)/256, 256>>>();
    // att1 (stored fp16)
    k_att1<<<dim3((B*P)/64, A_DIM/64), 256>>>(features, enc_w, enc_b);

    // ---- decode steps ----
    for (int t = 0; t < T; t++) {
        // att2 = h @ dec_w^T + dec_b
        k_gemm64<<<dim3(A_DIM/32, 1), 256>>>(p_h, H, dec_w, H, dec_b, p_att2, A_DIM, H, 0, t, lengths, outy);
        // gate = sigmoid(h @ f_beta_w^T + f_beta_b)
        k_gemm64<<<dim3(D/32, 1), 256>>>(p_h, H, f_beta_w, H, f_beta_b, p_gate, D, H, 1, t, lengths, outy);
        // e scores
        k_e<<<(B*P*32 + 255)/256, 256>>>(att_w, att_b);
        // softmax + awe (+ alpha output)
        k_awe<<<dim3(B, 4), 256>>>(lengths, outa, t);
        // gates = xh @ Wcat^T (K split in 2 for occupancy; deterministic 2-buffer sum)
        k_gemm64<<<dim3(G4/32, 2), 256>>>(p_xh, XH, p_Wcat, XH, (const float*)0, p_gparts, G4, XH/2, 0, t, lengths, outy);
        // LSTM pointwise + stage next emb
        k_lstm<<<(B*H + 255)/256, 256>>>(t);
        // y = h2 @ cls_w^T + cls_b  (masked, written straight to output)
        k_gemm64<<<dim3((V + 31)/32, 1), 256>>>(p_h, H, cls_w, H, cls_b, (float*)0, V, H, 2, t, lengths, outy);
    }
}

// round 3
// speedup vs baseline: 2.5537x; 2.5537x over previous
#include <cuda_runtime.h>
#include <cuda_fp16.h>
#include <math.h>

#define B     64
#define P     196
#define D     2048
#define A_DIM 512
#define H     512
#define E     512
#define V     10000
#define VPAD  10048  /* 157*64 */
#define T     19
#define LCAP  20
#define XH    3072   /* E + D + H */
#define G4    2048   /* 4*H       */
#define NSMALL 2560  /* A_DIM + D */
#define KSPLIT 4

// ---------------- scratch (device globals) ----------------------------------
__device__ __half g_featsh[(size_t)B*P*D];       // features fp16 (51.4 MB)
__device__ __half g_att1h[(size_t)B*P*A_DIM];    // att1 fp16 (12.8 MB)
__device__ __half g_Wcath[(size_t)G4*XH];        // [W_ih|W_hh] fp16 (12.6 MB)
__device__ __half g_clswh[(size_t)VPAD*H];       // cls_w fp16, zero-padded rows
__device__ __half g_encwh[(size_t)A_DIM*D];      // enc_w fp16
__device__ __half g_smallw[(size_t)NSMALL*H];    // [dec_w | f_beta_w] fp16
__device__ float  g_smallb[NSMALL];              // [dec_b | f_beta_b]
__device__ float  g_bcat[G4];                    // b_ih + b_hh
__device__ __half g_embh[(size_t)B*T*E];         // gathered embeddings fp16
__device__ __half g_xhh[(size_t)B*XH];           // [emb | awe | h] fp16
__device__ float  g_small_out[(size_t)B*NSMALL]; // [att2 | gate] fp32
__device__ float  g_meanf[B*D];
__device__ float  g_h0[B*H];
__device__ float  g_c[B*H];
__device__ float  g_e[B*P];
__device__ float  g_gparts[(size_t)KSPLIT*B*G4]; // split-K partials

// ---------------- one-time kernels ------------------------------------------
__global__ void k_f2h(const float* __restrict__ f)
{
    size_t i = (size_t)blockIdx.x * blockDim.x + threadIdx.x;
    size_t n4 = (size_t)B*P*D/4;
    if (i < n4) {
        float4 v = ((const float4*)f)[i];
        __half2* o = (__half2*)g_featsh + 2*i;
        o[0] = __floats2half2_rn(v.x, v.y);
        o[1] = __floats2half2_rn(v.z, v.w);
    }
}

__global__ void k_mean(const float* __restrict__ f)
{
    int i = blockIdx.x * blockDim.x + threadIdx.x;
    if (i < B*D) {
        int b = i >> 11, d = i & (D-1);
        const float* p = f + (size_t)b*P*D + d;
        float s = 0.f;
        #pragma unroll 4
        for (int q = 0; q < P; q++) s += p[(size_t)q*D];
        g_meanf[i] = s * (1.f/196.f);
    }
}

__global__ void k_embh(const float* __restrict__ emb, const int* __restrict__ captions)
{
    int i = blockIdx.x * blockDim.x + threadIdx.x;
    if (i < B*T*E) {
        int e  = i & (E-1);
        int bt = i >> 9;
        int b = bt / T, t = bt % T;
        int tok = captions[b*LCAP + t];
        g_embh[i] = __float2half(emb[(size_t)tok*E + e]);
    }
}

__global__ void k_wcath(const float* __restrict__ W_ih, const float* __restrict__ b_ih,
                        const float* __restrict__ W_hh, const float* __restrict__ b_hh)
{
    size_t i = (size_t)blockIdx.x * blockDim.x + threadIdx.x;
    if (i < (size_t)G4*XH) {
        int j = (int)(i / XH), k = (int)(i % XH);
        float v = (k < E + D) ? W_ih[(size_t)j*(E+D) + k]
                              : W_hh[(size_t)j*H + (k - (E+D))];
        g_Wcath[i] = __float2half(v);
        if (k == 0) g_bcat[j] = b_ih[j] + b_hh[j];
    }
}

__global__ void k_clsh(const float* __restrict__ cls_w)
{
    size_t i = (size_t)blockIdx.x * blockDim.x + threadIdx.x;
    if (i < (size_t)VPAD*H) {
        int n = (int)(i / H);
        g_clswh[i] = (n < V) ? __float2half(cls_w[i]) : __half(0.f);
    }
}

__global__ void k_ench(const float* __restrict__ enc_w)
{
    size_t i = (size_t)blockIdx.x * blockDim.x + threadIdx.x;
    if (i < (size_t)A_DIM*D) g_encwh[i] = __float2half(enc_w[i]);
}

__global__ void k_smallwh(const float* __restrict__ dec_w, const float* __restrict__ dec_b,
                          const float* __restrict__ fb_w,  const float* __restrict__ fb_b)
{
    size_t i = (size_t)blockIdx.x * blockDim.x + threadIdx.x;
    if (i < (size_t)NSMALL*H) {
        int n = (int)(i / H), k = (int)(i % H);
        float v = (n < A_DIM) ? dec_w[(size_t)n*H + k] : fb_w[(size_t)(n - A_DIM)*H + k];
        g_smallw[i] = __float2half(v);
        if (k == 0) g_smallb[n] = (n < A_DIM) ? dec_b[n] : fb_b[n - A_DIM];
    }
}

__global__ void k_initxh()
{
    int i = blockIdx.x * blockDim.x + threadIdx.x;
    if (i < B*H) {
        int b = i >> 9, j = i & (H-1);
        g_xhh[b*XH + j]         = g_embh[(size_t)(b*T + 0)*E + j];
        g_xhh[b*XH + E + D + j] = __float2half(g_h0[i]);
    }
}

// ---------------- fp32 skinny GEMM (one-time h0/c0 only) --------------------
__global__ void k_gemm64(const float* __restrict__ Ain, int ldA,
                         const float* __restrict__ W, int ldW,
                         const float* __restrict__ bias,
                         float* __restrict__ C, int N, int K)
{
    __shared__ float As[32][68];
    __shared__ float Ws[32][36];
    const int tid = threadIdx.x;
    const int n0  = blockIdx.x * 32;
    const int am = tid >> 2, akq = (tid & 3) * 4;
    const int wn = tid >> 3, wkq = (tid & 7) * 4;
    const int tm4 = (tid >> 4) * 4;
    const int tn2 = (tid & 15) * 2;
    float acc[4][2] = {};
    for (int kc = 0; kc < K; kc += 32) {
        const float* ap = Ain + (size_t)am*ldA + kc;
        float4 a0 = *(const float4*)(ap + akq);
        float4 a1 = *(const float4*)(ap + 16 + akq);
        float4 w0 = *(const float4*)(W + (size_t)(n0+wn)*ldW + kc + wkq);
        __syncthreads();
        As[akq+0][am]=a0.x; As[akq+1][am]=a0.y; As[akq+2][am]=a0.z; As[akq+3][am]=a0.w;
        As[16+akq+0][am]=a1.x; As[16+akq+1][am]=a1.y; As[16+akq+2][am]=a1.z; As[16+akq+3][am]=a1.w;
        Ws[wkq+0][wn]=w0.x; Ws[wkq+1][wn]=w0.y; Ws[wkq+2][wn]=w0.z; Ws[wkq+3][wn]=w0.w;
        __syncthreads();
        #pragma unroll
        for (int kk = 0; kk < 32; kk++) {
            float4 a = *(const float4*)&As[kk][tm4];
            float b0 = Ws[kk][tn2], b1 = Ws[kk][tn2+1];
            acc[0][0]+=a.x*b0; acc[0][1]+=a.x*b1;
            acc[1][0]+=a.y*b0; acc[1][1]+=a.y*b1;
            acc[2][0]+=a.z*b0; acc[2][1]+=a.z*b1;
            acc[3][0]+=a.w*b0; acc[3][1]+=a.w*b1;
        }
    }
    #pragma unroll
    for (int r = 0; r < 4; r++)
        #pragma unroll
        for (int cc = 0; cc < 2; cc++) {
            int m = tm4 + r, n = n0 + tn2 + cc;
            C[(size_t)m*N + n] = acc[r][cc] + bias[n];
        }
}

// ---------------- HMMA GEMM: C(M,N) = A(M,K) @ W(N,K)^T, fp16 in / fp32 acc -
// BM=64 BN=64 BK=32, 8 warps (2x4), warp tile 32x16 via m16n8k16.
// blockIdx.x = n tile, blockIdx.y = K split, blockIdx.z = m tile.
// mode 0: fp32 partial -> C + blockIdx.y*64*N        (bias ignored)
// mode 1: fused small: n<A_DIM -> att2, else sigmoid->gate, both into C(+bias)
// mode 2: cls masked:  outy[m*T*V + t*V + n] = act ? c+bias : 0   (n<V)
// mode 3: att1: g_att1h[m*A_DIM+n] = half(c + bias)
__device__ __forceinline__ void mma16816(float c[4], const unsigned a[4], const unsigned b[2])
{
    asm volatile(
        "mma.sync.aligned.m16n8k16.row.col.f32.f16.f16.f32 "
        "{%0,%1,%2,%3}, {%4,%5,%6,%7}, {%8,%9}, {%0,%1,%2,%3};"
        : "+f"(c[0]), "+f"(c[1]), "+f"(c[2]), "+f"(c[3])
        : "r"(a[0]), "r"(a[1]), "r"(a[2]), "r"(a[3]), "r"(b[0]), "r"(b[1]));
}

__global__ void k_hgemm(const __half* __restrict__ Ain, int ldA,
                        const __half* __restrict__ W, int ldW,
                        const float* __restrict__ bias,
                        float* __restrict__ C,
                        int N, int K, int mode, int t,
                        const int* __restrict__ lengths,
                        float* __restrict__ outy)
{
    __shared__ __half As[64][40];
    __shared__ __half Ws[64][40];
    const int tid  = threadIdx.x;
    const int lane = tid & 31;
    const int wid  = tid >> 5;
    const int wm   = wid >> 2;        // 0..1
    const int wn   = wid & 3;         // 0..3
    const int grp  = lane >> 2;       // 0..7
    const int qp   = lane & 3;        // 0..3
    const int n0   = blockIdx.x * 64;
    const int m0   = blockIdx.z * 64;
    const int koff = blockIdx.y * K;

    const int lrow = tid >> 2;          // 0..63
    const int lcol = (tid & 3) * 8;     // 0,8,16,24

    float acc[2][2][4] = {};

    for (int kc = 0; kc < K; kc += 32) {
        uint4 av = *(const uint4*)(Ain + (size_t)(m0 + lrow)*ldA + koff + kc + lcol);
        uint4 wv = make_uint4(0u, 0u, 0u, 0u);
        if (n0 + lrow < N)
            wv = *(const uint4*)(W + (size_t)(n0 + lrow)*ldW + koff + kc + lcol);
        __syncthreads();
        *(uint4*)&As[lrow][lcol] = av;
        *(uint4*)&Ws[lrow][lcol] = wv;
        __syncthreads();
        #pragma unroll
        for (int ks = 0; ks < 2; ks++) {
            const int kb = 16*ks + 2*qp;
            unsigned afr[2][4], bfr[2][2];
            #pragma unroll
            for (int mf = 0; mf < 2; mf++) {
                const int r = 32*wm + 16*mf + grp;
                afr[mf][0] = *(const unsigned*)&As[r    ][kb    ];
                afr[mf][1] = *(const unsigned*)&As[r + 8][kb    ];
                afr[mf][2] = *(const unsigned*)&As[r    ][kb + 8];
                afr[mf][3] = *(const unsigned*)&As[r + 8][kb + 8];
            }
            #pragma unroll
            for (int nf = 0; nf < 2; nf++) {
                const int r = 16*wn + 8*nf + grp;
                bfr[nf][0] = *(const unsigned*)&Ws[r][kb    ];
                bfr[nf][1] = *(const unsigned*)&Ws[r][kb + 8];
            }
            #pragma unroll
            for (int mf = 0; mf < 2; mf++)
                #pragma unroll
                for (int nf = 0; nf < 2; nf++)
                    mma16816(acc[mf][nf], afr[mf], bfr[nf]);
        }
    }

    // epilogue
    #pragma unroll
    for (int mf = 0; mf < 2; mf++)
        #pragma unroll
        for (int nf = 0; nf < 2; nf++)
            #pragma unroll
            for (int q = 0; q < 4; q++) {
                const int m = m0 + 32*wm + 16*mf + grp + (q >> 1) * 8;
                const int n = n0 + 16*wn + 8*nf + 2*qp + (q & 1);
                float v = acc[mf][nf][q];
                if (mode == 0) {
                    C[(size_t)blockIdx.y*64*N + (size_t)(m - m0)*N + n] = v;
                } else if (mode == 1) {
                    v += bias[n];
                    if (n >= A_DIM) v = 1.f / (1.f + expf(-v));
                    C[(size_t)(m - m0)*NSMALL + n] = v;
                } else if (mode == 2) {
                    if (n < V) {
                        int act = t < (lengths[m - m0] - 1);
                        outy[(size_t)(m - m0)*T*V + (size_t)t*V + n] = act ? (v + bias[n]) : 0.f;
                    }
                } else { // mode 3: att1
                    g_att1h[(size_t)m*A_DIM + n] = __float2half(v + bias[n]);
                }
            }
}

// ---------------- e[b,p] = att_w . relu(att1[b,p,:] + att2[b,:]) + att_b ----
__global__ void k_e(const float* __restrict__ attw, const float* __restrict__ attb)
{
    int gw = (blockIdx.x * blockDim.x + threadIdx.x) >> 5;
    int lane = threadIdx.x & 31;
    if (gw >= B*P) return;
    int b = gw / P;
    const __half* a1 = g_att1h + (size_t)gw * A_DIM;
    const float*  a2 = g_small_out + (size_t)b * NSMALL;   // att2 = cols [0,512)
    float s = 0.f;
    #pragma unroll 4
    for (int a = lane; a < A_DIM; a += 32) {
        float v = __half2float(a1[a]) + a2[a];
        if (v > 0.f) s += v * attw[a];
    }
    #pragma unroll
    for (int o = 16; o; o >>= 1) s += __shfl_xor_sync(0xffffffffu, s, o);
    if (lane == 0) g_e[gw] = s + attb[0];
}

// ---------------- softmax(e) -> alpha; awe = gate * (alpha @ feats) ----------
__global__ void k_awe(const int* __restrict__ lengths, float* __restrict__ out_alpha, int t)
{
    int b = blockIdx.x, chunk = blockIdx.y, tid = threadIdx.x;
    __shared__ float sred[256];
    __shared__ float sal[P];
    float ev = (tid < P) ? g_e[b*P + tid] : -1e30f;
    sred[tid] = ev; __syncthreads();
    for (int s = 128; s > 0; s >>= 1) { if (tid < s) sred[tid] = fmaxf(sred[tid], sred[tid+s]); __syncthreads(); }
    float mx = sred[0]; __syncthreads();
    float ex = (tid < P) ? expf(ev - mx) : 0.f;
    sred[tid] = ex; __syncthreads();
    for (int s = 128; s > 0; s >>= 1) { if (tid < s) sred[tid] += sred[tid+s]; __syncthreads(); }
    float inv = 1.f / sred[0];
    if (tid < P) sal[tid] = ex * inv;
    __syncthreads();

    const __half2* fp2 = (const __half2*)g_featsh + (size_t)b*P*(D/2) + chunk*256 + tid;
    float2 acc = make_float2(0.f, 0.f);
    #pragma unroll 4
    for (int p = 0; p < P; p++) {
        float2 f = __half22float2(fp2[(size_t)p*(D/2)]);
        float al = sal[p];
        acc.x += al * f.x; acc.y += al * f.y;
    }
    int d = chunk*512 + 2*tid;
    acc.x *= g_small_out[(size_t)b*NSMALL + A_DIM + d];       // gate
    acc.y *= g_small_out[(size_t)b*NSMALL + A_DIM + d + 1];
    *(__half2*)&g_xhh[(size_t)b*XH + E + d] = __floats2half2_rn(acc.x, acc.y);

    if (chunk == 0 && tid < P) {
        int act = t < (lengths[b] - 1);
        out_alpha[((size_t)b*T + t)*P + tid] = act ? sal[tid] : 0.f;
    }
}

// ---------------- LSTM pointwise update + next-step emb staging -------------
__global__ void k_lstm(int t)
{
    int i = blockIdx.x * blockDim.x + threadIdx.x;
    if (i >= B*H) return;
    int b = i >> 9, j = i & (H-1);
    float gi = g_bcat[j], gf = g_bcat[j + H], gg = g_bcat[j + 2*H], go = g_bcat[j + 3*H];
    #pragma unroll
    for (int s = 0; s < KSPLIT; s++) {
        const float* p = g_gparts + (size_t)s*B*G4 + (size_t)b*G4;
        gi += p[j]; gf += p[j + H]; gg += p[j + 2*H]; go += p[j + 3*H];
    }
    float si = 1.f / (1.f + expf(-gi));
    float sf = 1.f / (1.f + expf(-gf));
    float so = 1.f / (1.f + expf(-go));
    float c2 = sf * g_c[i] + si * tanhf(gg);
    float h2 = so * tanhf(c2);
    g_c[i] = c2;
    g_xhh[(size_t)b*XH + E + D + j] = __float2half(h2);
    if (t + 1 < T) g_xhh[(size_t)b*XH + j] = g_embh[(size_t)(b*T + (t+1))*E + j];
}

// ---------------- host driver ------------------------------------------------
extern "C" void kernel_launch(void* const* d_in, const int* in_sizes, int n_in,
                              void* d_out, int out_size)
{
    const float* features = (const float*)d_in[0];
    const int*   captions = (const int*)  d_in[1];
    const int*   lengths  = (const int*)  d_in[2];
    const float* emb      = (const float*)d_in[3];
    const float* W_ih     = (const float*)d_in[4];
    const float* b_ih     = (const float*)d_in[5];
    const float* W_hh     = (const float*)d_in[6];
    const float* b_hh     = (const float*)d_in[7];
    const float* h_fc_w   = (const float*)d_in[8];
    const float* h_fc_b   = (const float*)d_in[9];
    const float* c_fc_w   = (const float*)d_in[10];
    const float* c_fc_b   = (const float*)d_in[11];
    const float* f_beta_w = (const float*)d_in[12];
    const float* f_beta_b = (const float*)d_in[13];
    const float* cls_w    = (const float*)d_in[14];
    const float* cls_b    = (const float*)d_in[15];
    const float* enc_w    = (const float*)d_in[16];
    const float* enc_b    = (const float*)d_in[17];
    const float* dec_w    = (const float*)d_in[18];
    const float* dec_b    = (const float*)d_in[19];
    const float* att_w    = (const float*)d_in[20];
    const float* att_b    = (const float*)d_in[21];

    float* outy = (float*)d_out;
    float* outa = outy + (size_t)B*T*V;

    float *p_meanf, *p_h0, *p_c, *p_smallb, *p_gparts, *p_small_out;
    __half *p_featsh, *p_Wcath, *p_clswh, *p_encwh, *p_smallw, *p_xhh;
    cudaGetSymbolAddress((void**)&p_meanf,     g_meanf);
    cudaGetSymbolAddress((void**)&p_h0,        g_h0);
    cudaGetSymbolAddress((void**)&p_c,         g_c);
    cudaGetSymbolAddress((void**)&p_smallb,    g_smallb);
    cudaGetSymbolAddress((void**)&p_gparts,    g_gparts);
    cudaGetSymbolAddress((void**)&p_small_out, g_small_out);
    cudaGetSymbolAddress((void**)&p_featsh,    g_featsh);
    cudaGetSymbolAddress((void**)&p_Wcath,     g_Wcath);
    cudaGetSymbolAddress((void**)&p_clswh,     g_clswh);
    cudaGetSymbolAddress((void**)&p_encwh,     g_encwh);
    cudaGetSymbolAddress((void**)&p_smallw,    g_smallw);
    cudaGetSymbolAddress((void**)&p_xhh,       g_xhh);

    // ---- one-time preprocessing ----
    k_f2h    <<<(int)(((size_t)B*P*D/4 + 255)/256), 256>>>(features);
    k_mean   <<<(B*D + 255)/256, 256>>>(features);
    k_embh   <<<(B*T*E + 255)/256, 256>>>(emb, captions);
    k_wcath  <<<(int)(((size_t)G4*XH + 255)/256), 256>>>(W_ih, b_ih, W_hh, b_hh);
    k_clsh   <<<(int)(((size_t)VPAD*H + 255)/256), 256>>>(cls_w);
    k_ench   <<<(int)(((size_t)A_DIM*D + 255)/256), 256>>>(enc_w);
    k_smallwh<<<(int)(((size_t)NSMALL*H + 255)/256), 256>>>(dec_w, dec_b, f_beta_w, f_beta_b);
    // h0 / c0 in fp32 (one-time, keeps init state exact)
    k_gemm64<<<H/32, 256>>>(p_meanf, D, h_fc_w, D, h_fc_b, p_h0, H, D);
    k_gemm64<<<H/32, 256>>>(p_meanf, D, c_fc_w, D, c_fc_b, p_c,  H, D);
    k_initxh<<<(B*H + 255)/256, 256>>>();
    // att1 via HMMA (fp16 out)
    k_hgemm<<<dim3(A_DIM/64, 1, (B*P)/64), 256>>>(
        p_featsh, D, p_encwh, D, enc_b, (float*)0, A_DIM, D, 3, 0, lengths, outy);

    // ---- decode steps ----
    for (int t = 0; t < T; t++) {
        // att2 + gate fused: [dec_w | f_beta_w] @ h
        k_hgemm<<<dim3(NSMALL/64, 1, 1), 256>>>(
            p_xhh + (E + D), XH, p_smallw, H, p_smallb, p_small_out,
            NSMALL, H, 1, t, lengths, outy);
        // e scores
        k_e<<<(B*P*32 + 255)/256, 256>>>(att_w, att_b);
        // softmax + awe (+ alpha output)
        k_awe<<<dim3(B, 4), 256>>>(lengths, outa, t);
        // gates = xh @ Wcat^T, split-K=4 fp32 partials
        k_hgemm<<<dim3(G4/64, KSPLIT, 1), 256>>>(
            p_xhh, XH, p_Wcath, XH, (const float*)0, p_gparts,
            G4, XH/KSPLIT, 0, t, lengths, outy);
        // LSTM pointwise + stage next emb
        k_lstm<<<(B*H + 255)/256, 256>>>(t);
        // y = h2 @ cls_w^T + cls_b (masked, direct to output)
        k_hgemm<<<dim3(VPAD/64, 1, 1), 256>>>(
            p_xhh + (E + D), XH, p_clswh, H, cls_b, (float*)0,
            V, H, 2, t, lengths, outy);
    }
}